// round 9
// baseline (speedup 1.0000x reference)
#include <cstdint>
#include <cuda_runtime.h>
#include <cuda_bf16.h>

// ---------------------------------------------------------------------------
// GnnEncoder: 3-layer GraphSAGE (mean aggr) + ReLU + LayerNorm.
// R9: activations kept as hi/lo bf16 pairs everywhere (exact to 2^-17);
// GEMM = bf16x3 emulation (Ah*Bh + Ah*Bl + Al*Bh, fp32 acc) with cp.async
// double-buffered tiles; CSR chain fused (convert+hist, scan+invc).
// (R8 passed: 307.7us, rel_err 9.9e-6.)
// ---------------------------------------------------------------------------

static constexpr int NN = 50000;
static constexpr int EE = 800000;
static constexpr int C  = 128;

// scratch (static __device__ allocations: allowed)
__device__ __nv_bfloat16 g_xh[NN * C];
__device__ __nv_bfloat16 g_xl[NN * C];
__device__ __nv_bfloat16 g_h1h[NN * C];
__device__ __nv_bfloat16 g_h1l[NN * C];
__device__ __nv_bfloat16 g_h2h[NN * C];
__device__ __nv_bfloat16 g_h2l[NN * C];
__device__ __nv_bfloat16 g_mh[NN * C];
__device__ __nv_bfloat16 g_ml[NN * C];
__device__ __nv_bfloat16 g_w1h[128 * 256];
__device__ __nv_bfloat16 g_w1l[128 * 256];
__device__ __nv_bfloat16 g_w2h[128 * 256];
__device__ __nv_bfloat16 g_w2l[128 * 256];
__device__ __nv_bfloat16 g_w3h[64 * 256];
__device__ __nv_bfloat16 g_w3l[64 * 256];
__device__ int   g_src[EE];
__device__ int   g_dst[EE];
__device__ int   g_csr[EE];
__device__ int   g_off[NN + 1];
__device__ int   g_cnt[NN];
__device__ int   g_cur[NN];
__device__ float g_invc[NN];
__device__ int   g_is64;

// --------------------------- index prep ------------------------------------

__global__ void k_detect(const unsigned* __restrict__ buf) {
    int nz = 0;
    for (int i = threadIdx.x; i < 512; i += blockDim.x)
        if (buf[2 * i + 1] != 0u) nz = 1;
    nz = __syncthreads_or(nz);
    if (threadIdx.x == 0) g_is64 = (nz == 0) ? 1 : 0;
}

__global__ void k_zero(int n) {
    int i = blockIdx.x * blockDim.x + threadIdx.x;
    if (i < n) { g_cnt[i] = 0; g_cur[i] = 0; }
}

// convert edge indices to int32 AND histogram dst (fused)
__global__ void k_convert(const void* __restrict__ buf, int E) {
    int e = blockIdx.x * blockDim.x + threadIdx.x;
    if (e >= E) return;
    int s, d;
    if (g_is64) {
        const long long* p = (const long long*)buf;
        s = (int)p[e]; d = (int)p[E + e];
    } else {
        const int* p = (const int*)buf;
        s = p[e]; d = p[E + e];
    }
    g_src[e] = s; g_dst[e] = d;
    atomicAdd(&g_cnt[d], 1);
}

// single-block exclusive scan of g_cnt -> g_off; also writes g_invc (fused)
__global__ void k_scan(int n) {
    __shared__ int sh[1024];
    __shared__ int s_carry;
    const int tid = threadIdx.x;
    if (tid == 0) s_carry = 0;
    __syncthreads();
    for (int base = 0; base < n; base += 1024) {
        int c = s_carry;
        int i = base + tid;
        int v = (i < n) ? g_cnt[i] : 0;
        sh[tid] = v;
        __syncthreads();
        for (int off = 1; off < 1024; off <<= 1) {
            int t = (tid >= off) ? sh[tid - off] : 0;
            __syncthreads();
            sh[tid] += t;
            __syncthreads();
        }
        int incl = sh[tid];
        if (i < n) {
            g_off[i] = c + incl - v;   // exclusive
            g_invc[i] = 1.0f / (float)(v > 0 ? v : 1);
        }
        if (tid == 0) s_carry = c + sh[1023];
        __syncthreads();
    }
    if (tid == 0) g_off[n] = s_carry;
}

__global__ void k_scatter(int E) {
    int e = blockIdx.x * blockDim.x + threadIdx.x;
    if (e >= E) return;
    int d = g_dst[e];
    int p = atomicAdd(&g_cur[d], 1);
    g_csr[g_off[d] + p] = g_src[e];
}

// --------------------------- conversions -----------------------------------

__device__ __forceinline__ void split_pair(float a, float b,
                                           __nv_bfloat162& h, __nv_bfloat162& l) {
    __nv_bfloat16 ha = __float2bfloat16(a), hb = __float2bfloat16(b);
    h = __nv_bfloat162(ha, hb);
    l = __nv_bfloat162(__float2bfloat16(a - __bfloat162float(ha)),
                       __float2bfloat16(b - __bfloat162float(hb)));
}

// x (fp32) -> hi/lo bf16 arrays
__global__ void k_cvt_x(const float* __restrict__ x, int total) {
    int i = (blockIdx.x * blockDim.x + threadIdx.x) * 4;
    if (i >= total) return;
    float4 v = *(const float4*)(x + i);
    __nv_bfloat162 h0, l0, h1, l1;
    split_pair(v.x, v.y, h0, l0);
    split_pair(v.z, v.w, h1, l1);
    uint2 oh, ol;
    oh.x = *(unsigned*)&h0; oh.y = *(unsigned*)&h1;
    ol.x = *(unsigned*)&l0; ol.y = *(unsigned*)&l1;
    *(uint2*)(g_xh + i) = oh;
    *(uint2*)(g_xl + i) = ol;
}

// weights: dst[n][k] (k<128: Wl, else Wr) -> hi + residual lo
__global__ void k_cvt_w(const float* __restrict__ Wl, const float* __restrict__ Wr,
                        __nv_bfloat16* __restrict__ dh, __nv_bfloat16* __restrict__ dl,
                        int N) {
    int i = blockIdx.x * blockDim.x + threadIdx.x;
    if (i >= N * 256) return;
    int nrow = i >> 8, k = i & 255;
    float v = (k < 128) ? Wl[nrow * 128 + k] : Wr[nrow * 128 + (k - 128)];
    __nv_bfloat16 h = __float2bfloat16(v);
    dh[i] = h;
    dl[i] = __float2bfloat16(v - __bfloat162float(h));
}

// --------------------------- aggregation -----------------------------------
// warp-per-node mean over hi/lo bf16 rows; v = hi + lo (fp32 accumulate).
// 128 bf16 per row = uint2 (4 bf16) per lane per array.
__global__ __launch_bounds__(256) void k_agg(int insel, int n) {
    const __nv_bfloat16* xh = (insel == 0) ? g_xh : (insel == 1) ? g_h1h : g_h2h;
    const __nv_bfloat16* xl = (insel == 0) ? g_xl : (insel == 1) ? g_h1l : g_h2l;
    int warp = (blockIdx.x * blockDim.x + threadIdx.x) >> 5;
    int lane = threadIdx.x & 31;
    if (warp >= n) return;
    int s0 = g_off[warp], s1 = g_off[warp + 1];
    const uint2* xh2 = (const uint2*)xh;
    const uint2* xl2 = (const uint2*)xl;
    float a0 = 0.f, a1 = 0.f, a2 = 0.f, a3 = 0.f;
    for (int i = s0; i < s1; i++) {
        int a = g_csr[i];
        uint2 uh = xh2[a * 32 + lane];
        uint2 ul = xl2[a * 32 + lane];
        float2 h0 = __bfloat1622float2(*(__nv_bfloat162*)&uh.x);
        float2 h1 = __bfloat1622float2(*(__nv_bfloat162*)&uh.y);
        float2 l0 = __bfloat1622float2(*(__nv_bfloat162*)&ul.x);
        float2 l1 = __bfloat1622float2(*(__nv_bfloat162*)&ul.y);
        a0 += h0.x + l0.x; a1 += h0.y + l0.y;
        a2 += h1.x + l1.x; a3 += h1.y + l1.y;
    }
    float ic = g_invc[warp];
    a0 *= ic; a1 *= ic; a2 *= ic; a3 *= ic;
    __nv_bfloat162 h0, l0, h1, l1;
    split_pair(a0, a1, h0, l0);
    split_pair(a2, a3, h1, l1);
    uint2 oh, ol;
    oh.x = *(unsigned*)&h0; oh.y = *(unsigned*)&h1;
    ol.x = *(unsigned*)&l0; ol.y = *(unsigned*)&l1;
    ((uint2*)g_mh)[warp * 32 + lane] = oh;
    ((uint2*)g_ml)[warp * 32 + lane] = ol;
}

// --------------------------- tensor-core GEMM (bf16x3) ----------------------

__device__ __forceinline__ void mma16816(float* c, const unsigned* a, const unsigned* b) {
    asm volatile(
        "mma.sync.aligned.m16n8k16.row.col.f32.bf16.bf16.f32 "
        "{%0,%1,%2,%3}, {%4,%5,%6,%7}, {%8,%9}, {%0,%1,%2,%3};\n"
        : "+f"(c[0]), "+f"(c[1]), "+f"(c[2]), "+f"(c[3])
        : "r"(a[0]), "r"(a[1]), "r"(a[2]), "r"(a[3]), "r"(b[0]), "r"(b[1]));
}
__device__ __forceinline__ void ldsm4(unsigned* r, uint32_t addr) {
    asm volatile("ldmatrix.sync.aligned.m8n8.x4.shared.b16 {%0,%1,%2,%3}, [%4];\n"
        : "=r"(r[0]), "=r"(r[1]), "=r"(r[2]), "=r"(r[3]) : "r"(addr));
}
__device__ __forceinline__ void cp16(uint32_t saddr, const void* gptr, int srcsz) {
    asm volatile("cp.async.cg.shared.global [%0], [%1], 16, %2;\n"
        :: "r"(saddr), "l"(gptr), "r"(srcsz));
}
__device__ __forceinline__ void cp_commit() {
    asm volatile("cp.async.commit_group;\n");
}
template <int N>
__device__ __forceinline__ void cp_wait() {
    asm volatile("cp.async.wait_group %0;\n" :: "n"(N));
}

// out[m][j] = sum_k mean[m][k]*W[j][k] + sum_k Ax[m][k]*W[j][128+k] + bias[j]
// FUSE: + ReLU + LayerNorm -> hi/lo bf16 arrays; else fp32 out.
// BM=128, BK=32, 256 threads (8 warps), warp tile m16 x nBN (whole rows).
// Double-buffered cp.async pipeline, 2 stages in dynamic smem.
template <int BN, bool FUSE>
__global__ __launch_bounds__(256) void k_mma(
    const __nv_bfloat16* __restrict__ Axh, const __nv_bfloat16* __restrict__ Axl,
    const __nv_bfloat16* __restrict__ Wh,  const __nv_bfloat16* __restrict__ Wl_,
    const float* __restrict__ bias,
    const float* __restrict__ gamma, const float* __restrict__ beta,
    float* __restrict__ outf,
    __nv_bfloat16* __restrict__ outh, __nv_bfloat16* __restrict__ outl, int n)
{
    constexpr int BM = 128, BK = 32;
    constexpr int LDA = BK + 8;            // 40 bf16 (80B) row stride, 16B-mult
    constexpr int NT = BN / 8;
    // element offsets within one stage
    constexpr int AH = 0;
    constexpr int AL = BM * LDA;
    constexpr int BH = 2 * BM * LDA;
    constexpr int BL = 2 * BM * LDA + BN * LDA;
    constexpr int STAGE = 2 * BM * LDA + 2 * BN * LDA;      // elements
    constexpr int STAGE_B = STAGE * 2;                       // bytes

    extern __shared__ __align__(16) __nv_bfloat16 smem[];

    const int tid = threadIdx.x;
    const int lane = tid & 31, warp = tid >> 5;
    const int rowBase = blockIdx.x * BM;
    const uint32_t sBase = (uint32_t)__cvta_generic_to_shared(smem);

    float c[NT][4];
#pragma unroll
    for (int j = 0; j < NT; j++)
#pragma unroll
        for (int q = 0; q < 4; q++) c[j][q] = 0.f;

    // tile loader: K-step t into stage s (cp.async, 16B ops)
    auto load_tile = [&](int t, int s) {
        const __nv_bfloat16* Ah = (t < 4) ? g_mh : Axh;
        const __nv_bfloat16* Al = (t < 4) ? g_ml : Axl;
        const int k0 = (t & 3) * BK;
        const uint32_t st = sBase + s * STAGE_B;
        // A: BM rows x 32 cols; 4 threads/row, 16B each
#pragma unroll
        for (int i = 0; i < (BM * 4) / 256; i++) {
            int q = tid + i * 256;
            int row = q >> 2, c8 = q & 3;
            int gr = rowBase + row;
            int sz = (gr < n) ? 16 : 0;
            uint32_t so = (uint32_t)((row * LDA + c8 * 8) * 2);
            cp16(st + AH * 2 + so, Ah + gr * 128 + k0 + c8 * 8, sz);
            cp16(st + AL * 2 + so, Al + gr * 128 + k0 + c8 * 8, sz);
        }
        // B: BN rows x 32 cols
#pragma unroll
        for (int i = 0; i < (BN * 4) / 256; i++) {
            int q = tid + i * 256;
            int row = q >> 2, c8 = q & 3;
            uint32_t so = (uint32_t)((row * LDA + c8 * 8) * 2);
            cp16(st + BH * 2 + so, Wh  + row * 256 + t * BK + c8 * 8, 16);
            cp16(st + BL * 2 + so, Wl_ + row * 256 + t * BK + c8 * 8, 16);
        }
    };

    const uint32_t aOff =
        (uint32_t)(((warp * 16 + (lane & 15)) * LDA + ((lane >> 4) << 3)) * 2);
    const int bRow = (lane & 7) + ((lane >> 4) << 3);
    const int bKof = ((lane >> 3) & 1) << 3;

    load_tile(0, 0);
    cp_commit();

    for (int t = 0; t < 8; t++) {
        const int s = t & 1;
        if (t + 1 < 8) {
            load_tile(t + 1, (t + 1) & 1);
            cp_commit();
            cp_wait<1>();
        } else {
            cp_wait<0>();
        }
        __syncthreads();

        const uint32_t st = sBase + s * STAGE_B;
#pragma unroll
        for (int kk = 0; kk < BK; kk += 16) {
            unsigned ah[4], al[4];
            ldsm4(ah, st + AH * 2 + aOff + (uint32_t)(kk * 2));
            ldsm4(al, st + AL * 2 + aOff + (uint32_t)(kk * 2));
#pragma unroll
            for (int jp = 0; jp < NT / 2; jp++) {
                unsigned bh[4], bl[4];
                uint32_t bo = (uint32_t)(((jp * 16 + bRow) * LDA + kk + bKof) * 2);
                ldsm4(bh, st + BH * 2 + bo);
                ldsm4(bl, st + BL * 2 + bo);
                mma16816(c[2 * jp], ah, bh);
                mma16816(c[2 * jp], ah, bl);
                mma16816(c[2 * jp], al, bh);
                mma16816(c[2 * jp + 1], ah, bh + 2);
                mma16816(c[2 * jp + 1], ah, bl + 2);
                mma16816(c[2 * jp + 1], al, bh + 2);
            }
        }
        __syncthreads();
    }

    // ---- epilogue ----
    const int r0 = rowBase + warp * 16 + (lane >> 2);
    const int r1 = r0 + 8;
    const int cb = (lane & 3) * 2;

    if constexpr (FUSE) {
        float s0 = 0.f, ss0 = 0.f, s1 = 0.f, ss1 = 0.f;
#pragma unroll
        for (int j = 0; j < NT; j++) {
            float b0 = bias[j * 8 + cb], b1 = bias[j * 8 + cb + 1];
            c[j][0] = fmaxf(c[j][0] + b0, 0.f);
            c[j][1] = fmaxf(c[j][1] + b1, 0.f);
            c[j][2] = fmaxf(c[j][2] + b0, 0.f);
            c[j][3] = fmaxf(c[j][3] + b1, 0.f);
            s0 += c[j][0] + c[j][1]; ss0 += c[j][0] * c[j][0] + c[j][1] * c[j][1];
            s1 += c[j][2] + c[j][3]; ss1 += c[j][2] * c[j][2] + c[j][3] * c[j][3];
        }
#pragma unroll
        for (int o = 1; o <= 2; o <<= 1) {
            s0 += __shfl_xor_sync(0xffffffffu, s0, o);
            ss0 += __shfl_xor_sync(0xffffffffu, ss0, o);
            s1 += __shfl_xor_sync(0xffffffffu, s1, o);
            ss1 += __shfl_xor_sync(0xffffffffu, ss1, o);
        }
        const float inv = 1.0f / 128.0f;
        float mu0 = s0 * inv, var0 = ss0 * inv - mu0 * mu0;
        float mu1 = s1 * inv, var1 = ss1 * inv - mu1 * mu1;
        float rs0 = rsqrtf(var0 + 1e-5f);
        float rs1 = rsqrtf(var1 + 1e-5f);
#pragma unroll
        for (int j = 0; j < NT; j++) {
            float g0 = gamma[j * 8 + cb], g1v = gamma[j * 8 + cb + 1];
            float e0 = beta[j * 8 + cb],  e1 = beta[j * 8 + cb + 1];
            if (r0 < n) {
                float v0 = (c[j][0] - mu0) * rs0 * g0 + e0;
                float v1 = (c[j][1] - mu0) * rs0 * g1v + e1;
                __nv_bfloat162 h, l;
                split_pair(v0, v1, h, l);
                *(__nv_bfloat162*)(outh + r0 * 128 + j * 8 + cb) = h;
                *(__nv_bfloat162*)(outl + r0 * 128 + j * 8 + cb) = l;
            }
            if (r1 < n) {
                float v0 = (c[j][2] - mu1) * rs1 * g0 + e0;
                float v1 = (c[j][3] - mu1) * rs1 * g1v + e1;
                __nv_bfloat162 h, l;
                split_pair(v0, v1, h, l);
                *(__nv_bfloat162*)(outh + r1 * 128 + j * 8 + cb) = h;
                *(__nv_bfloat162*)(outl + r1 * 128 + j * 8 + cb) = l;
            }
        }
    } else {
#pragma unroll
        for (int j = 0; j < NT; j++) {
            float b0 = bias[j * 8 + cb], b1 = bias[j * 8 + cb + 1];
            if (r0 < n)
                *(float2*)(outf + r0 * BN + j * 8 + cb) =
                    make_float2(c[j][0] + b0, c[j][1] + b1);
            if (r1 < n)
                *(float2*)(outf + r1 * BN + j * 8 + cb) =
                    make_float2(c[j][2] + b0, c[j][3] + b1);
        }
    }
}

// --------------------------- launch ----------------------------------------

extern "C" void kernel_launch(void* const* d_in, const int* in_sizes, int n_in,
                              void* d_out, int out_size)
{
    const float* x   = (const float*)d_in[0];
    const void*  ei  = d_in[1];
    const float* Wl1 = (const float*)d_in[2];
    const float* bl1 = (const float*)d_in[3];
    const float* Wr1 = (const float*)d_in[4];
    const float* Wl2 = (const float*)d_in[5];
    const float* bl2 = (const float*)d_in[6];
    const float* Wr2 = (const float*)d_in[7];
    const float* Wl3 = (const float*)d_in[8];
    const float* bl3 = (const float*)d_in[9];
    const float* Wr3 = (const float*)d_in[10];
    const float* g1  = (const float*)d_in[11];
    const float* be1 = (const float*)d_in[12];
    const float* g2  = (const float*)d_in[13];
    const float* be2 = (const float*)d_in[14];

    const int n = in_sizes[0] / C;       // 50000
    const int E = in_sizes[1] / 2;       // 800000

    const int TB = 256;

    // dynamic smem sizes (2 stages)
    constexpr int LDA = 40;
    const int smem128 = 2 * (2 * 128 * LDA + 2 * 128 * LDA) * 2;   // 81920 B
    const int smem64  = 2 * (2 * 128 * LDA + 2 * 64  * LDA) * 2;   // 61440 B
    static bool attr_done = false;
    if (!attr_done) {
        cudaFuncSetAttribute(k_mma<128, true>,
            cudaFuncAttributeMaxDynamicSharedMemorySize, smem128);
        cudaFuncSetAttribute(k_mma<64, false>,
            cudaFuncAttributeMaxDynamicSharedMemorySize, smem64);
        attr_done = true;
    }

    // ---- CSR build (fused) + conversions ----
    k_detect<<<1, TB>>>((const unsigned*)ei);
    k_zero<<<(n + TB - 1) / TB, TB>>>(n);
    k_convert<<<(E + TB - 1) / TB, TB>>>(ei, E);      // + hist
    k_scan<<<1, 1024>>>(n);                            // + invc
    k_scatter<<<(E + TB - 1) / TB, TB>>>(E);

    k_cvt_x<<<(n * C / 4 + TB - 1) / TB, TB>>>(x, n * C);
    __nv_bfloat16 *w1h, *w1l, *w2h, *w2l, *w3h, *w3l;
    cudaGetSymbolAddress((void**)&w1h, g_w1h);
    cudaGetSymbolAddress((void**)&w1l, g_w1l);
    cudaGetSymbolAddress((void**)&w2h, g_w2h);
    cudaGetSymbolAddress((void**)&w2l, g_w2l);
    cudaGetSymbolAddress((void**)&w3h, g_w3h);
    cudaGetSymbolAddress((void**)&w3l, g_w3l);
    k_cvt_w<<<(128 * 256 + TB - 1) / TB, TB>>>(Wl1, Wr1, w1h, w1l, 128);
    k_cvt_w<<<(128 * 256 + TB - 1) / TB, TB>>>(Wl2, Wr2, w2h, w2l, 128);
    k_cvt_w<<<(64 * 256 + TB - 1) / TB, TB>>>(Wl3, Wr3, w3h, w3l, 64);

    __nv_bfloat16 *xh, *xl, *h1h, *h1l, *h2h, *h2l;
    cudaGetSymbolAddress((void**)&xh, g_xh);
    cudaGetSymbolAddress((void**)&xl, g_xl);
    cudaGetSymbolAddress((void**)&h1h, g_h1h);
    cudaGetSymbolAddress((void**)&h1l, g_h1l);
    cudaGetSymbolAddress((void**)&h2h, g_h2h);
    cudaGetSymbolAddress((void**)&h2l, g_h2l);

    const int aggGrid  = (n + 7) / 8;       // 8 warps/block, warp per node
    const int gemmGrid = (n + 127) / 128;

    // ---- layer 1 ----
    k_agg<<<aggGrid, TB>>>(0, n);
    k_mma<128, true><<<gemmGrid, TB, smem128>>>(xh, xl, w1h, w1l, bl1, g1, be1,
                                                nullptr, h1h, h1l, n);
    // ---- layer 2 ----
    k_agg<<<aggGrid, TB>>>(1, n);
    k_mma<128, true><<<gemmGrid, TB, smem128>>>(h1h, h1l, w2h, w2l, bl2, g2, be2,
                                                nullptr, h2h, h2l, n);
    // ---- layer 3 (64 outputs, no ReLU/LN) ----
    k_agg<<<aggGrid, TB>>>(2, n);
    k_mma<64, false><<<gemmGrid, TB, smem64>>>(h2h, h2l, w3h, w3l, bl3,
                                               nullptr, nullptr,
                                               (float*)d_out, nullptr, nullptr, n);
}

// round 10
// speedup vs baseline: 1.3704x; 1.3704x over previous
#include <cstdint>
#include <cuda_runtime.h>
#include <cuda_bf16.h>

// ---------------------------------------------------------------------------
// GnnEncoder: 3-layer GraphSAGE (mean aggr) + ReLU + LayerNorm.
// R10 = R8 (best: 307.7us) with ONE change: the single-block scan (measured
// 84.7us, serial on 1 SM) replaced by a 3-kernel hierarchical scan (~5us).
// GEMM: bf16x3 emulation (Ah*Bh+Ah*Bl+Al*Bh, fp32 acc), fp32 tensors in mem.
// ---------------------------------------------------------------------------

static constexpr int NN = 50000;
static constexpr int EE = 800000;
static constexpr int C  = 128;

// scratch (static __device__ allocations: allowed)
__device__ float g_mean[NN * C];
__device__ float g_h1[NN * C];
__device__ float g_h2[NN * C];
__device__ __nv_bfloat16 g_w1h[128 * 256];
__device__ __nv_bfloat16 g_w1l[128 * 256];
__device__ __nv_bfloat16 g_w2h[128 * 256];
__device__ __nv_bfloat16 g_w2l[128 * 256];
__device__ __nv_bfloat16 g_w3h[64 * 256];
__device__ __nv_bfloat16 g_w3l[64 * 256];
__device__ int   g_src[EE];
__device__ int   g_dst[EE];
__device__ int   g_csr[EE];
__device__ int   g_off[NN + 1];
__device__ int   g_cnt[NN];
__device__ int   g_cur[NN];
__device__ int   g_bsum[64];
__device__ int   g_bsumx[64];
__device__ float g_invc[NN];
__device__ int   g_is64;

// --------------------------- index prep ------------------------------------

// Detect int64 vs int32 storage of edge_index: node ids < 50000, so for
// int64 little-endian every odd 32-bit word is 0 across 512 samples.
__global__ void k_detect(const unsigned* __restrict__ buf) {
    int nz = 0;
    for (int i = threadIdx.x; i < 512; i += blockDim.x)
        if (buf[2 * i + 1] != 0u) nz = 1;
    nz = __syncthreads_or(nz);
    if (threadIdx.x == 0) g_is64 = (nz == 0) ? 1 : 0;
}

__global__ void k_zero(int n) {
    int i = blockIdx.x * blockDim.x + threadIdx.x;
    if (i < n) { g_cnt[i] = 0; g_cur[i] = 0; }
}

// convert edge indices to int32 AND histogram dst (fused)
__global__ void k_convert(const void* __restrict__ buf, int E) {
    int e = blockIdx.x * blockDim.x + threadIdx.x;
    if (e >= E) return;
    int s, d;
    if (g_is64) {
        const long long* p = (const long long*)buf;
        s = (int)p[e]; d = (int)p[E + e];
    } else {
        const int* p = (const int*)buf;
        s = p[e]; d = p[E + e];
    }
    g_src[e] = s; g_dst[e] = d;
    atomicAdd(&g_cnt[d], 1);
}

// ---- hierarchical scan: 49 blocks x 1024 -> 64-wide block-sum scan -> add ----
__global__ __launch_bounds__(1024) void k_scan1(int n) {
    __shared__ int sh[1024];
    const int tid = threadIdx.x;
    int i = blockIdx.x * 1024 + tid;
    int v = (i < n) ? g_cnt[i] : 0;
    sh[tid] = v;
    __syncthreads();
    for (int off = 1; off < 1024; off <<= 1) {
        int t = (tid >= off) ? sh[tid - off] : 0;
        __syncthreads();
        sh[tid] += t;
        __syncthreads();
    }
    if (i < n) g_off[i] = sh[tid] - v;        // exclusive within block
    if (tid == 1023) g_bsum[blockIdx.x] = sh[1023];
}

__global__ void k_scan2(int nb) {
    __shared__ int sh[64];
    const int tid = threadIdx.x;
    int v = (tid < nb) ? g_bsum[tid] : 0;
    sh[tid] = v;
    __syncthreads();
    for (int off = 1; off < 64; off <<= 1) {
        int t = (tid >= off) ? sh[tid - off] : 0;
        __syncthreads();
        sh[tid] += t;
        __syncthreads();
    }
    if (tid < nb) g_bsumx[tid] = sh[tid] - v; // exclusive
}

// add block offsets; also compute invc (fused). g_off[n] = E (known total).
__global__ void k_scan3(int n, int E) {
    int i = blockIdx.x * blockDim.x + threadIdx.x;
    if (i < n) {
        g_off[i] += g_bsumx[i >> 10];
        int cnt = g_cnt[i];
        g_invc[i] = 1.0f / (float)(cnt > 0 ? cnt : 1);
    }
    if (i == 0) g_off[n] = E;
}

__global__ void k_scatter(int E) {
    int e = blockIdx.x * blockDim.x + threadIdx.x;
    if (e >= E) return;
    int d = g_dst[e];
    int p = atomicAdd(&g_cur[d], 1);
    g_csr[g_off[d] + p] = g_src[e];
}

// --------------------------- weight split ----------------------------------
// dst[n][k] (k<128: Wl, else Wr) split into bf16 hi + bf16 residual lo.
__global__ void k_cvt_w(const float* __restrict__ Wl, const float* __restrict__ Wr,
                        __nv_bfloat16* __restrict__ dh, __nv_bfloat16* __restrict__ dl,
                        int N) {
    int i = blockIdx.x * blockDim.x + threadIdx.x;
    if (i >= N * 256) return;
    int nrow = i >> 8, k = i & 255;
    float v = (k < 128) ? Wl[nrow * 128 + k] : Wr[nrow * 128 + (k - 128)];
    __nv_bfloat16 h = __float2bfloat16(v);
    dh[i] = h;
    dl[i] = __float2bfloat16(v - __bfloat162float(h));
}

// --------------------------- aggregation (fp32) -----------------------------
// warp-per-node mean of neighbor rows (128 f32 = float4 per lane).
__global__ __launch_bounds__(256) void k_agg(const float* __restrict__ xext,
                                             int insel, int n) {
    const float* xin = (insel == 0) ? xext : (insel == 1) ? g_h1 : g_h2;
    int warp = (blockIdx.x * blockDim.x + threadIdx.x) >> 5;
    int lane = threadIdx.x & 31;
    if (warp >= n) return;
    int s0 = g_off[warp], s1 = g_off[warp + 1];
    const float4* xin4 = (const float4*)xin;
    float4 acc = make_float4(0.f, 0.f, 0.f, 0.f);
    int i = s0;
    for (; i + 1 < s1; i += 2) {
        int a = g_csr[i], b = g_csr[i + 1];
        float4 va = xin4[a * 32 + lane];
        float4 vb = xin4[b * 32 + lane];
        acc.x += va.x + vb.x; acc.y += va.y + vb.y;
        acc.z += va.z + vb.z; acc.w += va.w + vb.w;
    }
    if (i < s1) {
        int a = g_csr[i];
        float4 va = xin4[a * 32 + lane];
        acc.x += va.x; acc.y += va.y; acc.z += va.z; acc.w += va.w;
    }
    float ic = g_invc[warp];
    acc.x *= ic; acc.y *= ic; acc.z *= ic; acc.w *= ic;
    ((float4*)g_mean)[warp * 32 + lane] = acc;
}

// --------------------------- tensor-core GEMM (bf16x3) ----------------------

__device__ __forceinline__ void mma16816(float* c, const unsigned* a, const unsigned* b) {
    asm volatile(
        "mma.sync.aligned.m16n8k16.row.col.f32.bf16.bf16.f32 "
        "{%0,%1,%2,%3}, {%4,%5,%6,%7}, {%8,%9}, {%0,%1,%2,%3};\n"
        : "+f"(c[0]), "+f"(c[1]), "+f"(c[2]), "+f"(c[3])
        : "r"(a[0]), "r"(a[1]), "r"(a[2]), "r"(a[3]), "r"(b[0]), "r"(b[1]));
}
__device__ __forceinline__ void ldsm4(unsigned* r, uint32_t addr) {
    asm volatile("ldmatrix.sync.aligned.m8n8.x4.shared.b16 {%0,%1,%2,%3}, [%4];\n"
        : "=r"(r[0]), "=r"(r[1]), "=r"(r[2]), "=r"(r[3]) : "r"(addr));
}

// out[m][j] = sum_k mean[m][k]*W[j][k] + sum_k Ax[m][k]*W[j][128+k] + bias[j]
// FUSE: + ReLU + LayerNorm. A operands fp32 in gmem, split hi/lo at tile load.
// BM=128, BK=32, 256 threads (8 warps), warp tile m16 x nBN (whole rows).
template <int BN, bool FUSE>
__global__ __launch_bounds__(256) void k_mma(
    const float* __restrict__ Ax,
    const __nv_bfloat16* __restrict__ Wh,      // [BN][256] concat [Wl|Wr] hi
    const __nv_bfloat16* __restrict__ Wl_,     // lo
    const float* __restrict__ bias,
    const float* __restrict__ gamma, const float* __restrict__ beta,
    float* __restrict__ out, int n)
{
    constexpr int BM = 128, BK = 32;
    constexpr int LDA = BK + 8;            // 40 bf16 row stride (80B, 16B-mult)
    constexpr int NT = BN / 8;             // n-tiles per warp row stripe

    __shared__ __align__(16) __nv_bfloat16 Ash[BM * LDA];
    __shared__ __align__(16) __nv_bfloat16 Asl[BM * LDA];
    __shared__ __align__(16) __nv_bfloat16 Bsh[BN * LDA];
    __shared__ __align__(16) __nv_bfloat16 Bsl[BN * LDA];

    const int tid = threadIdx.x;
    const int lane = tid & 31, warp = tid >> 5;
    const int rowBase = blockIdx.x * BM;

    float c[NT][4];
#pragma unroll
    for (int j = 0; j < NT; j++)
#pragma unroll
        for (int q = 0; q < 4; q++) c[j][q] = 0.f;

    const uint32_t ahBase = (uint32_t)__cvta_generic_to_shared(Ash);
    const uint32_t alBase = (uint32_t)__cvta_generic_to_shared(Asl);
    const uint32_t bhBase = (uint32_t)__cvta_generic_to_shared(Bsh);
    const uint32_t blBase = (uint32_t)__cvta_generic_to_shared(Bsl);
    const uint32_t aOff =
        (uint32_t)(((warp * 16 + (lane & 15)) * LDA + ((lane >> 4) << 3)) * 2);
    const int bRow = (lane & 7) + ((lane >> 4) << 3);   // n within 16-tile
    const int bKof = ((lane >> 3) & 1) << 3;            // k offset 0/8

    // 8 K-steps of 32: t=0..3 -> (g_mean, W[:,0:128]); t=4..7 -> (Ax, W[:,128:])
    for (int t = 0; t < 8; t++) {
        const float* A = (t < 4) ? g_mean : Ax;
        const int k0 = (t & 3) * BK;

        // A tile: BM x 32 fp32 -> split to bf16 hi/lo. 8 values per thread-chunk.
#pragma unroll
        for (int i = 0; i < (BM * 4) / 256; i++) {
            int q = tid + i * 256;
            int row = q >> 2, c8 = q & 3;
            float v[8];
            int gr = rowBase + row;
            if (gr < n) {
                float4 v0 = *(const float4*)(A + gr * 128 + k0 + c8 * 8);
                float4 v1 = *(const float4*)(A + gr * 128 + k0 + c8 * 8 + 4);
                v[0] = v0.x; v[1] = v0.y; v[2] = v0.z; v[3] = v0.w;
                v[4] = v1.x; v[5] = v1.y; v[6] = v1.z; v[7] = v1.w;
            } else {
#pragma unroll
                for (int j = 0; j < 8; j++) v[j] = 0.f;
            }
            __nv_bfloat16 h[8], l[8];
#pragma unroll
            for (int j = 0; j < 8; j++) {
                h[j] = __float2bfloat16(v[j]);
                l[j] = __float2bfloat16(v[j] - __bfloat162float(h[j]));
            }
            *(uint4*)(&Ash[row * LDA + c8 * 8]) = *(uint4*)h;
            *(uint4*)(&Asl[row * LDA + c8 * 8]) = *(uint4*)l;
        }
        // B tile: BN x 32 from pre-split weights
#pragma unroll
        for (int i = 0; i < (BN * 4) / 256; i++) {
            int q = tid + i * 256;
            int row = q >> 2, c8 = q & 3;
            *(uint4*)(&Bsh[row * LDA + c8 * 8]) =
                *(const uint4*)(Wh + row * 256 + t * 32 + c8 * 8);
            *(uint4*)(&Bsl[row * LDA + c8 * 8]) =
                *(const uint4*)(Wl_ + row * 256 + t * 32 + c8 * 8);
        }
        __syncthreads();

#pragma unroll
        for (int kk = 0; kk < BK; kk += 16) {
            unsigned ah[4], al[4];
            ldsm4(ah, ahBase + aOff + (uint32_t)(kk * 2));
            ldsm4(al, alBase + aOff + (uint32_t)(kk * 2));
#pragma unroll
            for (int jp = 0; jp < NT / 2; jp++) {
                unsigned bh[4], bl[4];
                uint32_t bo = (uint32_t)(((jp * 16 + bRow) * LDA + kk + bKof) * 2);
                ldsm4(bh, bhBase + bo);
                ldsm4(bl, blBase + bo);
                mma16816(c[2 * jp], ah, bh);
                mma16816(c[2 * jp], ah, bl);
                mma16816(c[2 * jp], al, bh);
                mma16816(c[2 * jp + 1], ah, bh + 2);
                mma16816(c[2 * jp + 1], ah, bl + 2);
                mma16816(c[2 * jp + 1], al, bh + 2);
            }
        }
        __syncthreads();
    }

    // ---- epilogue ----
    const int r0 = rowBase + warp * 16 + (lane >> 2);
    const int r1 = r0 + 8;
    const int cb = (lane & 3) * 2;

    if constexpr (FUSE) {
        float s0 = 0.f, ss0 = 0.f, s1 = 0.f, ss1 = 0.f;
#pragma unroll
        for (int j = 0; j < NT; j++) {
            float b0 = bias[j * 8 + cb], b1 = bias[j * 8 + cb + 1];
            c[j][0] = fmaxf(c[j][0] + b0, 0.f);
            c[j][1] = fmaxf(c[j][1] + b1, 0.f);
            c[j][2] = fmaxf(c[j][2] + b0, 0.f);
            c[j][3] = fmaxf(c[j][3] + b1, 0.f);
            s0 += c[j][0] + c[j][1]; ss0 += c[j][0] * c[j][0] + c[j][1] * c[j][1];
            s1 += c[j][2] + c[j][3]; ss1 += c[j][2] * c[j][2] + c[j][3] * c[j][3];
        }
#pragma unroll
        for (int o = 1; o <= 2; o <<= 1) {
            s0 += __shfl_xor_sync(0xffffffffu, s0, o);
            ss0 += __shfl_xor_sync(0xffffffffu, ss0, o);
            s1 += __shfl_xor_sync(0xffffffffu, s1, o);
            ss1 += __shfl_xor_sync(0xffffffffu, ss1, o);
        }
        const float inv = 1.0f / 128.0f;
        float mu0 = s0 * inv, var0 = ss0 * inv - mu0 * mu0;
        float mu1 = s1 * inv, var1 = ss1 * inv - mu1 * mu1;
        float rs0 = rsqrtf(var0 + 1e-5f);
        float rs1 = rsqrtf(var1 + 1e-5f);
#pragma unroll
        for (int j = 0; j < NT; j++) {
            float g0 = gamma[j * 8 + cb], g1v = gamma[j * 8 + cb + 1];
            float e0 = beta[j * 8 + cb],  e1 = beta[j * 8 + cb + 1];
            if (r0 < n)
                *(float2*)(out + r0 * 128 + j * 8 + cb) = make_float2(
                    (c[j][0] - mu0) * rs0 * g0 + e0,
                    (c[j][1] - mu0) * rs0 * g1v + e1);
            if (r1 < n)
                *(float2*)(out + r1 * 128 + j * 8 + cb) = make_float2(
                    (c[j][2] - mu1) * rs1 * g0 + e0,
                    (c[j][3] - mu1) * rs1 * g1v + e1);
        }
    } else {
#pragma unroll
        for (int j = 0; j < NT; j++) {
            float b0 = bias[j * 8 + cb], b1 = bias[j * 8 + cb + 1];
            if (r0 < n)
                *(float2*)(out + r0 * BN + j * 8 + cb) =
                    make_float2(c[j][0] + b0, c[j][1] + b1);
            if (r1 < n)
                *(float2*)(out + r1 * BN + j * 8 + cb) =
                    make_float2(c[j][2] + b0, c[j][3] + b1);
        }
    }
}

// --------------------------- launch ----------------------------------------

extern "C" void kernel_launch(void* const* d_in, const int* in_sizes, int n_in,
                              void* d_out, int out_size)
{
    const float* x   = (const float*)d_in[0];
    const void*  ei  = d_in[1];
    const float* Wl1 = (const float*)d_in[2];
    const float* bl1 = (const float*)d_in[3];
    const float* Wr1 = (const float*)d_in[4];
    const float* Wl2 = (const float*)d_in[5];
    const float* bl2 = (const float*)d_in[6];
    const float* Wr2 = (const float*)d_in[7];
    const float* Wl3 = (const float*)d_in[8];
    const float* bl3 = (const float*)d_in[9];
    const float* Wr3 = (const float*)d_in[10];
    const float* g1  = (const float*)d_in[11];
    const float* be1 = (const float*)d_in[12];
    const float* g2  = (const float*)d_in[13];
    const float* be2 = (const float*)d_in[14];

    const int n = in_sizes[0] / C;       // 50000
    const int E = in_sizes[1] / 2;       // 800000

    const int TB = 256;
    const int nb = (n + 1023) / 1024;    // 49 scan blocks

    // ---- CSR build (parallel scan) + weight split ----
    k_detect<<<1, TB>>>((const unsigned*)ei);
    k_zero<<<(n + TB - 1) / TB, TB>>>(n);
    k_convert<<<(E + TB - 1) / TB, TB>>>(ei, E);      // + hist
    k_scan1<<<nb, 1024>>>(n);
    k_scan2<<<1, 64>>>(nb);
    k_scan3<<<(n + TB - 1) / TB, TB>>>(n, E);          // + invc
    k_scatter<<<(E + TB - 1) / TB, TB>>>(E);

    __nv_bfloat16 *w1h, *w1l, *w2h, *w2l, *w3h, *w3l;
    cudaGetSymbolAddress((void**)&w1h, g_w1h);
    cudaGetSymbolAddress((void**)&w1l, g_w1l);
    cudaGetSymbolAddress((void**)&w2h, g_w2h);
    cudaGetSymbolAddress((void**)&w2l, g_w2l);
    cudaGetSymbolAddress((void**)&w3h, g_w3h);
    cudaGetSymbolAddress((void**)&w3l, g_w3l);
    k_cvt_w<<<(128 * 256 + TB - 1) / TB, TB>>>(Wl1, Wr1, w1h, w1l, 128);
    k_cvt_w<<<(128 * 256 + TB - 1) / TB, TB>>>(Wl2, Wr2, w2h, w2l, 128);
    k_cvt_w<<<(64 * 256 + TB - 1) / TB, TB>>>(Wl3, Wr3, w3h, w3l, 64);

    float *h1p, *h2p;
    cudaGetSymbolAddress((void**)&h1p, g_h1);
    cudaGetSymbolAddress((void**)&h2p, g_h2);

    const int aggGrid  = (n + 7) / 8;       // 8 warps/block, warp per node
    const int gemmGrid = (n + 127) / 128;

    // ---- layer 1 ----
    k_agg<<<aggGrid, TB>>>(x, 0, n);
    k_mma<128, true><<<gemmGrid, TB>>>(x, w1h, w1l, bl1, g1, be1, h1p, n);
    // ---- layer 2 ----
    k_agg<<<aggGrid, TB>>>(x, 1, n);
    k_mma<128, true><<<gemmGrid, TB>>>(h1p, w2h, w2l, bl2, g2, be2, h2p, n);
    // ---- layer 3 (64 outputs, no ReLU/LN) ----
    k_agg<<<aggGrid, TB>>>(x, 2, n);
    k_mma<64, false><<<gemmGrid, TB>>>(h2p, w3h, w3l, bl3, nullptr, nullptr,
                                       (float*)d_out, n);
}

// round 12
// speedup vs baseline: 1.4255x; 1.0402x over previous
#include <cstdint>
#include <cuda_runtime.h>
#include <cuda_bf16.h>

// ---------------------------------------------------------------------------
// GnnEncoder: 3-layer GraphSAGE (mean aggr) + ReLU + LayerNorm.
// R11 = R10 (243.6us) with ONE change: k_mma pipelined.
//   - register prefetch of tile t+2 global loads
//   - smem double buffer: STS of tile t+1 overlaps compute of tile t
//   - one __syncthreads per K-step (was two + exposed LDG latency)
// GEMM math unchanged: bf16x3 emulation (Ah*Bh+Ah*Bl+Al*Bh, fp32 acc).
// ---------------------------------------------------------------------------

static constexpr int NN = 50000;
static constexpr int EE = 800000;
static constexpr int C  = 128;

// scratch (static __device__ allocations: allowed)
__device__ float g_mean[NN * C];
__device__ float g_h1[NN * C];
__device__ float g_h2[NN * C];
__device__ __nv_bfloat16 g_w1h[128 * 256];
__device__ __nv_bfloat16 g_w1l[128 * 256];
__device__ __nv_bfloat16 g_w2h[128 * 256];
__device__ __nv_bfloat16 g_w2l[128 * 256];
__device__ __nv_bfloat16 g_w3h[64 * 256];
__device__ __nv_bfloat16 g_w3l[64 * 256];
__device__ int   g_src[EE];
__device__ int   g_dst[EE];
__device__ int   g_csr[EE];
__device__ int   g_off[NN + 1];
__device__ int   g_cnt[NN];
__device__ int   g_cur[NN];
__device__ int   g_bsum[64];
__device__ int   g_bsumx[64];
__device__ float g_invc[NN];
__device__ int   g_is64;

// --------------------------- index prep ------------------------------------

__global__ void k_detect(const unsigned* __restrict__ buf) {
    int nz = 0;
    for (int i = threadIdx.x; i < 512; i += blockDim.x)
        if (buf[2 * i + 1] != 0u) nz = 1;
    nz = __syncthreads_or(nz);
    if (threadIdx.x == 0) g_is64 = (nz == 0) ? 1 : 0;
}

__global__ void k_zero(int n) {
    int i = blockIdx.x * blockDim.x + threadIdx.x;
    if (i < n) { g_cnt[i] = 0; g_cur[i] = 0; }
}

// convert edge indices to int32 AND histogram dst (fused)
__global__ void k_convert(const void* __restrict__ buf, int E) {
    int e = blockIdx.x * blockDim.x + threadIdx.x;
    if (e >= E) return;
    int s, d;
    if (g_is64) {
        const long long* p = (const long long*)buf;
        s = (int)p[e]; d = (int)p[E + e];
    } else {
        const int* p = (const int*)buf;
        s = p[e]; d = p[E + e];
    }
    g_src[e] = s; g_dst[e] = d;
    atomicAdd(&g_cnt[d], 1);
}

// ---- hierarchical scan: 49 blocks x 1024 -> 64-wide block-sum scan -> add ----
__global__ __launch_bounds__(1024) void k_scan1(int n) {
    __shared__ int sh[1024];
    const int tid = threadIdx.x;
    int i = blockIdx.x * 1024 + tid;
    int v = (i < n) ? g_cnt[i] : 0;
    sh[tid] = v;
    __syncthreads();
    for (int off = 1; off < 1024; off <<= 1) {
        int t = (tid >= off) ? sh[tid - off] : 0;
        __syncthreads();
        sh[tid] += t;
        __syncthreads();
    }
    if (i < n) g_off[i] = sh[tid] - v;        // exclusive within block
    if (tid == 1023) g_bsum[blockIdx.x] = sh[1023];
}

__global__ void k_scan2(int nb) {
    __shared__ int sh[64];
    const int tid = threadIdx.x;
    int v = (tid < nb) ? g_bsum[tid] : 0;
    sh[tid] = v;
    __syncthreads();
    for (int off = 1; off < 64; off <<= 1) {
        int t = (tid >= off) ? sh[tid - off] : 0;
        __syncthreads();
        sh[tid] += t;
        __syncthreads();
    }
    if (tid < nb) g_bsumx[tid] = sh[tid] - v; // exclusive
}

// add block offsets; also compute invc (fused). g_off[n] = E (known total).
__global__ void k_scan3(int n, int E) {
    int i = blockIdx.x * blockDim.x + threadIdx.x;
    if (i < n) {
        g_off[i] += g_bsumx[i >> 10];
        int cnt = g_cnt[i];
        g_invc[i] = 1.0f / (float)(cnt > 0 ? cnt : 1);
    }
    if (i == 0) g_off[n] = E;
}

__global__ void k_scatter(int E) {
    int e = blockIdx.x * blockDim.x + threadIdx.x;
    if (e >= E) return;
    int d = g_dst[e];
    int p = atomicAdd(&g_cur[d], 1);
    g_csr[g_off[d] + p] = g_src[e];
}

// --------------------------- weight split ----------------------------------
__global__ void k_cvt_w(const float* __restrict__ Wl, const float* __restrict__ Wr,
                        __nv_bfloat16* __restrict__ dh, __nv_bfloat16* __restrict__ dl,
                        int N) {
    int i = blockIdx.x * blockDim.x + threadIdx.x;
    if (i >= N * 256) return;
    int nrow = i >> 8, k = i & 255;
    float v = (k < 128) ? Wl[nrow * 128 + k] : Wr[nrow * 128 + (k - 128)];
    __nv_bfloat16 h = __float2bfloat16(v);
    dh[i] = h;
    dl[i] = __float2bfloat16(v - __bfloat162float(h));
}

// --------------------------- aggregation (fp32) -----------------------------
__global__ __launch_bounds__(256) void k_agg(const float* __restrict__ xext,
                                             int insel, int n) {
    const float* xin = (insel == 0) ? xext : (insel == 1) ? g_h1 : g_h2;
    int warp = (blockIdx.x * blockDim.x + threadIdx.x) >> 5;
    int lane = threadIdx.x & 31;
    if (warp >= n) return;
    int s0 = g_off[warp], s1 = g_off[warp + 1];
    const float4* xin4 = (const float4*)xin;
    float4 acc = make_float4(0.f, 0.f, 0.f, 0.f);
    int i = s0;
    for (; i + 1 < s1; i += 2) {
        int a = g_csr[i], b = g_csr[i + 1];
        float4 va = xin4[a * 32 + lane];
        float4 vb = xin4[b * 32 + lane];
        acc.x += va.x + vb.x; acc.y += va.y + vb.y;
        acc.z += va.z + vb.z; acc.w += va.w + vb.w;
    }
    if (i < s1) {
        int a = g_csr[i];
        float4 va = xin4[a * 32 + lane];
        acc.x += va.x; acc.y += va.y; acc.z += va.z; acc.w += va.w;
    }
    float ic = g_invc[warp];
    acc.x *= ic; acc.y *= ic; acc.z *= ic; acc.w *= ic;
    ((float4*)g_mean)[warp * 32 + lane] = acc;
}

// --------------------------- tensor-core GEMM (bf16x3) ----------------------

__device__ __forceinline__ void mma16816(float* c, const unsigned* a, const unsigned* b) {
    asm volatile(
        "mma.sync.aligned.m16n8k16.row.col.f32.bf16.bf16.f32 "
        "{%0,%1,%2,%3}, {%4,%5,%6,%7}, {%8,%9}, {%0,%1,%2,%3};\n"
        : "+f"(c[0]), "+f"(c[1]), "+f"(c[2]), "+f"(c[3])
        : "r"(a[0]), "r"(a[1]), "r"(a[2]), "r"(a[3]), "r"(b[0]), "r"(b[1]));
}
__device__ __forceinline__ void ldsm4(unsigned* r, uint32_t addr) {
    asm volatile("ldmatrix.sync.aligned.m8n8.x4.shared.b16 {%0,%1,%2,%3}, [%4];\n"
        : "=r"(r[0]), "=r"(r[1]), "=r"(r[2]), "=r"(r[3]) : "r"(addr));
}

// out[m][j] = sum_k mean[m][k]*W[j][k] + sum_k Ax[m][k]*W[j][128+k] + bias[j]
// FUSE: + ReLU + LayerNorm. A operands fp32 in gmem, split hi/lo at STS time.
// BM=128, BK=32, 256 threads (8 warps), warp tile m16 x nBN (whole rows).
// Pipeline: LDG tile t+2 -> regs, STS tile t+1 -> alt smem stage, compute t.
template <int BN, bool FUSE>
__global__ __launch_bounds__(256) void k_mma(
    const float* __restrict__ Ax,
    const __nv_bfloat16* __restrict__ Wh,      // [BN][256] concat [Wl|Wr] hi
    const __nv_bfloat16* __restrict__ Wl_,     // lo
    const float* __restrict__ bias,
    const float* __restrict__ gamma, const float* __restrict__ beta,
    float* __restrict__ out, int n)
{
    constexpr int BM = 128, BK = 32;
    constexpr int LDA = BK + 8;            // 40 bf16 row stride (80B, 16B-mult)
    constexpr int NT = BN / 8;             // n-tiles per warp row stripe
    constexpr int NB = (BN * 4) / 256;     // B chunks per thread (2 or 1)
    // element offsets within one stage
    constexpr int AH = 0;
    constexpr int AL = BM * LDA;
    constexpr int BH = 2 * BM * LDA;
    constexpr int BL = 2 * BM * LDA + BN * LDA;
    constexpr int STAGE = 2 * BM * LDA + 2 * BN * LDA;   // elements
    constexpr int STAGE_B = STAGE * 2;                    // bytes

    extern __shared__ __align__(16) __nv_bfloat16 smem[];

    const int tid = threadIdx.x;
    const int lane = tid & 31, warp = tid >> 5;
    const int rowBase = blockIdx.x * BM;
    const uint32_t sBase = (uint32_t)__cvta_generic_to_shared(smem);

    float c[NT][4];
#pragma unroll
    for (int j = 0; j < NT; j++)
#pragma unroll
        for (int q = 0; q < 4; q++) c[j][q] = 0.f;

    // prefetch registers
    float va[2][8];
    uint4 vbh[2], vbl[2];

    // global -> regs for K-step t
    auto ldg_tile = [&](int t) {
        const float* A = (t < 4) ? g_mean : Ax;
        const int k0 = (t & 3) * BK;
#pragma unroll
        for (int i = 0; i < 2; i++) {
            int q = tid + i * 256;
            int row = q >> 2, c8 = q & 3;
            int gr = rowBase + row;
            if (gr < n) {
                float4 v0 = *(const float4*)(A + gr * 128 + k0 + c8 * 8);
                float4 v1 = *(const float4*)(A + gr * 128 + k0 + c8 * 8 + 4);
                va[i][0] = v0.x; va[i][1] = v0.y; va[i][2] = v0.z; va[i][3] = v0.w;
                va[i][4] = v1.x; va[i][5] = v1.y; va[i][6] = v1.z; va[i][7] = v1.w;
            } else {
#pragma unroll
                for (int j = 0; j < 8; j++) va[i][j] = 0.f;
            }
        }
#pragma unroll
        for (int i = 0; i < NB; i++) {
            int q = tid + i * 256;
            int row = q >> 2, c8 = q & 3;
            vbh[i] = *(const uint4*)(Wh  + row * 256 + t * BK + c8 * 8);
            vbl[i] = *(const uint4*)(Wl_ + row * 256 + t * BK + c8 * 8);
        }
    };
    // regs -> smem stage s (with hi/lo split of A)
    auto sts_tile = [&](int s) {
        __nv_bfloat16* st = smem + s * STAGE;
#pragma unroll
        for (int i = 0; i < 2; i++) {
            int q = tid + i * 256;
            int row = q >> 2, c8 = q & 3;
            __nv_bfloat16 h[8], l[8];
#pragma unroll
            for (int j = 0; j < 8; j++) {
                h[j] = __float2bfloat16(va[i][j]);
                l[j] = __float2bfloat16(va[i][j] - __bfloat162float(h[j]));
            }
            *(uint4*)(st + AH + row * LDA + c8 * 8) = *(uint4*)h;
            *(uint4*)(st + AL + row * LDA + c8 * 8) = *(uint4*)l;
        }
#pragma unroll
        for (int i = 0; i < NB; i++) {
            int q = tid + i * 256;
            int row = q >> 2, c8 = q & 3;
            *(uint4*)(st + BH + row * LDA + c8 * 8) = vbh[i];
            *(uint4*)(st + BL + row * LDA + c8 * 8) = vbl[i];
        }
    };

    const uint32_t aOff =
        (uint32_t)(((warp * 16 + (lane & 15)) * LDA + ((lane >> 4) << 3)) * 2);
    const int bRow = (lane & 7) + ((lane >> 4) << 3);   // n within 16-tile
    const int bKof = ((lane >> 3) & 1) << 3;            // k offset 0/8

    // prologue: tile0 -> smem stage0, tile1 -> regs
    ldg_tile(0);
    sts_tile(0);
    ldg_tile(1);

    // 8 K-steps of 32: t=0..3 -> (g_mean, W[:,0:128]); t=4..7 -> (Ax, W[:,128:])
    for (int t = 0; t < 8; t++) {
        __syncthreads();   // stage t&1 ready; prior compute on other stage done
        if (t + 1 < 8) sts_tile((t + 1) & 1);   // overlaps compute below
        if (t + 2 < 8) ldg_tile(t + 2);         // in flight during compute

        const uint32_t st = sBase + (t & 1) * STAGE_B;
#pragma unroll
        for (int kk = 0; kk < BK; kk += 16) {
            unsigned ah[4], al[4];
            ldsm4(ah, st + AH * 2 + aOff + (uint32_t)(kk * 2));
            ldsm4(al, st + AL * 2 + aOff + (uint32_t)(kk * 2));
#pragma unroll
            for (int jp = 0; jp < NT / 2; jp++) {
                unsigned bh[4], bl[4];
                uint32_t bo = (uint32_t)(((jp * 16 + bRow) * LDA + kk + bKof) * 2);
                ldsm4(bh, st + BH * 2 + bo);
                ldsm4(bl, st + BL * 2 + bo);
                mma16816(c[2 * jp], ah, bh);
                mma16816(c[2 * jp], ah, bl);
                mma16816(c[2 * jp], al, bh);
                mma16816(c[2 * jp + 1], ah, bh + 2);
                mma16816(c[2 * jp + 1], ah, bl + 2);
                mma16816(c[2 * jp + 1], al, bh + 2);
            }
        }
    }

    // ---- epilogue ----
    const int r0 = rowBase + warp * 16 + (lane >> 2);
    const int r1 = r0 + 8;
    const int cb = (lane & 3) * 2;

    if constexpr (FUSE) {
        float s0 = 0.f, ss0 = 0.f, s1 = 0.f, ss1 = 0.f;
#pragma unroll
        for (int j = 0; j < NT; j++) {
            float b0 = bias[j * 8 + cb], b1 = bias[j * 8 + cb + 1];
            c[j][0] = fmaxf(c[j][0] + b0, 0.f);
            c[j][1] = fmaxf(c[j][1] + b1, 0.f);
            c[j][2] = fmaxf(c[j][2] + b0, 0.f);
            c[j][3] = fmaxf(c[j][3] + b1, 0.f);
            s0 += c[j][0] + c[j][1]; ss0 += c[j][0] * c[j][0] + c[j][1] * c[j][1];
            s1 += c[j][2] + c[j][3]; ss1 += c[j][2] * c[j][2] + c[j][3] * c[j][3];
        }
#pragma unroll
        for (int o = 1; o <= 2; o <<= 1) {
            s0 += __shfl_xor_sync(0xffffffffu, s0, o);
            ss0 += __shfl_xor_sync(0xffffffffu, ss0, o);
            s1 += __shfl_xor_sync(0xffffffffu, s1, o);
            ss1 += __shfl_xor_sync(0xffffffffu, ss1, o);
        }
        const float inv = 1.0f / 128.0f;
        float mu0 = s0 * inv, var0 = ss0 * inv - mu0 * mu0;
        float mu1 = s1 * inv, var1 = ss1 * inv - mu1 * mu1;
        float rs0 = rsqrtf(var0 + 1e-5f);
        float rs1 = rsqrtf(var1 + 1e-5f);
#pragma unroll
        for (int j = 0; j < NT; j++) {
            float g0 = gamma[j * 8 + cb], g1v = gamma[j * 8 + cb + 1];
            float e0 = beta[j * 8 + cb],  e1 = beta[j * 8 + cb + 1];
            if (r0 < n)
                *(float2*)(out + r0 * 128 + j * 8 + cb) = make_float2(
                    (c[j][0] - mu0) * rs0 * g0 + e0,
                    (c[j][1] - mu0) * rs0 * g1v + e1);
            if (r1 < n)
                *(float2*)(out + r1 * 128 + j * 8 + cb) = make_float2(
                    (c[j][2] - mu1) * rs1 * g0 + e0,
                    (c[j][3] - mu1) * rs1 * g1v + e1);
        }
    } else {
#pragma unroll
        for (int j = 0; j < NT; j++) {
            float b0 = bias[j * 8 + cb], b1 = bias[j * 8 + cb + 1];
            if (r0 < n)
                *(float2*)(out + r0 * BN + j * 8 + cb) =
                    make_float2(c[j][0] + b0, c[j][1] + b1);
            if (r1 < n)
                *(float2*)(out + r1 * BN + j * 8 + cb) =
                    make_float2(c[j][2] + b0, c[j][3] + b1);
        }
    }
}

// --------------------------- launch ----------------------------------------

extern "C" void kernel_launch(void* const* d_in, const int* in_sizes, int n_in,
                              void* d_out, int out_size)
{
    const float* x   = (const float*)d_in[0];
    const void*  ei  = d_in[1];
    const float* Wl1 = (const float*)d_in[2];
    const float* bl1 = (const float*)d_in[3];
    const float* Wr1 = (const float*)d_in[4];
    const float* Wl2 = (const float*)d_in[5];
    const float* bl2 = (const float*)d_in[6];
    const float* Wr2 = (const float*)d_in[7];
    const float* Wl3 = (const float*)d_in[8];
    const float* bl3 = (const float*)d_in[9];
    const float* Wr3 = (const float*)d_in[10];
    const float* g1  = (const float*)d_in[11];
    const float* be1 = (const float*)d_in[12];
    const float* g2  = (const float*)d_in[13];
    const float* be2 = (const float*)d_in[14];

    const int n = in_sizes[0] / C;       // 50000
    const int E = in_sizes[1] / 2;       // 800000

    const int TB = 256;
    const int nb = (n + 1023) / 1024;    // 49 scan blocks

    // dynamic smem (2 stages): BN=128 -> 81920B, BN=64 -> 61440B
    constexpr int LDA = 40;
    const int smem128 = 2 * (2 * 128 * LDA + 2 * 128 * LDA) * 2;
    const int smem64  = 2 * (2 * 128 * LDA + 2 * 64  * LDA) * 2;
    static bool attr_done = false;
    if (!attr_done) {
        cudaFuncSetAttribute(k_mma<128, true>,
            cudaFuncAttributeMaxDynamicSharedMemorySize, smem128);
        cudaFuncSetAttribute(k_mma<64, false>,
            cudaFuncAttributeMaxDynamicSharedMemorySize, smem64);
        attr_done = true;
    }

    // ---- CSR build (parallel scan) + weight split ----
    k_detect<<<1, TB>>>((const unsigned*)ei);
    k_zero<<<(n + TB - 1) / TB, TB>>>(n);
    k_convert<<<(E + TB - 1) / TB, TB>>>(ei, E);      // + hist
    k_scan1<<<nb, 1024>>>(n);
    k_scan2<<<1, 64>>>(nb);
    k_scan3<<<(n + TB - 1) / TB, TB>>>(n, E);          // + invc
    k_scatter<<<(E + TB - 1) / TB, TB>>>(E);

    __nv_bfloat16 *w1h, *w1l, *w2h, *w2l, *w3h, *w3l;
    cudaGetSymbolAddress((void**)&w1h, g_w1h);
    cudaGetSymbolAddress((void**)&w1l, g_w1l);
    cudaGetSymbolAddress((void**)&w2h, g_w2h);
    cudaGetSymbolAddress((void**)&w2l, g_w2l);
    cudaGetSymbolAddress((void**)&w3h, g_w3h);
    cudaGetSymbolAddress((void**)&w3l, g_w3l);
    k_cvt_w<<<(128 * 256 + TB - 1) / TB, TB>>>(Wl1, Wr1, w1h, w1l, 128);
    k_cvt_w<<<(128 * 256 + TB - 1) / TB, TB>>>(Wl2, Wr2, w2h, w2l, 128);
    k_cvt_w<<<(64 * 256 + TB - 1) / TB, TB>>>(Wl3, Wr3, w3h, w3l, 64);

    float *h1p, *h2p;
    cudaGetSymbolAddress((void**)&h1p, g_h1);
    cudaGetSymbolAddress((void**)&h2p, g_h2);

    const int aggGrid  = (n + 7) / 8;       // 8 warps/block, warp per node
    const int gemmGrid = (n + 127) / 128;

    // ---- layer 1 ----
    k_agg<<<aggGrid, TB>>>(x, 0, n);
    k_mma<128, true><<<gemmGrid, TB, smem128>>>(x, w1h, w1l, bl1, g1, be1, h1p, n);
    // ---- layer 2 ----
    k_agg<<<aggGrid, TB>>>(x, 1, n);
    k_mma<128, true><<<gemmGrid, TB, smem128>>>(h1p, w2h, w2l, bl2, g2, be2, h2p, n);
    // ---- layer 3 (64 outputs, no ReLU/LN) ----
    k_agg<<<aggGrid, TB>>>(x, 2, n);
    k_mma<64, false><<<gemmGrid, TB, smem64>>>(h2p, w3h, w3l, bl3, nullptr, nullptr,
                                               (float*)d_out, n);
}